// round 1
// baseline (speedup 1.0000x reference)
#include <cuda_runtime.h>
#include <math.h>

#define EPS 1e-8f
#define TR  (1.0f/1024.0f)
#define TC  (1.0f/256.0f)
#define SEG 4194304            // 16*1024*256

// ---------------- scratch (device globals; no allocation) ----------------
__device__ float g_M[8388608];      // exp(sim/tau), [32768 rows][256 cols], 32MB
__device__ float g_proto[131072];   // normalized protos [2][256][256]
__device__ float g_xinv[32768];     // 1/(||x||+eps) per row
__device__ float g_u[32768];
__device__ float g_v[8192];         // [2*16][256]
__device__ float g_colacc[8192];
__device__ float g_csum2[8192];     // colsums of final assign
__device__ float g_bs[32];          // per (mod,batch) sum of M

// exp(20*s) via 2^y with degree-7 Taylor of 2^f — no MUFU (keeps SFU pipe free)
__device__ __forceinline__ float exp20(float s) {
    float y  = s * 28.853900817779268f;      // 20 * log2(e)
    float fl = floorf(y);
    float f  = y - fl;
    // Taylor of 2^f = sum (ln2)^k f^k / k!, k=0..7  (rel err ~1.3e-6)
    float p = 1.5252733804059840e-05f;
    p = fmaf(p, f, 1.5403530393381609e-04f);
    p = fmaf(p, f, 1.3333558146428443e-03f);
    p = fmaf(p, f, 9.6181291076284772e-03f);
    p = fmaf(p, f, 5.5504108664821580e-02f);
    p = fmaf(p, f, 2.4022650695910071e-01f);
    p = fmaf(p, f, 6.9314718055994531e-01f);
    p = fmaf(p, f, 1.0f);
    int e = (int)fl + 127;
    return p * __int_as_float(e << 23);
}

// ---------------- tiny init ----------------
__global__ void k_zero() {
    int i = blockIdx.x * blockDim.x + threadIdx.x;
    if (i < 8192) { g_colacc[i] = 0.f; g_csum2[i] = 0.f; }
    if (i < 32)   g_bs[i] = 0.f;
}

// normalize prototypes: warp per row
__global__ void k_proto(const float* __restrict__ p_rgb, const float* __restrict__ p_sn) {
    int warp = (blockIdx.x * blockDim.x + threadIdx.x) >> 5;
    int lane = threadIdx.x & 31;
    if (warp >= 512) return;
    int mod = warp >> 8, row = warp & 255;
    const float* src = (mod ? p_sn : p_rgb) + row * 256;
    float v[8], s = 0.f;
#pragma unroll
    for (int j = 0; j < 8; j++) { v[j] = src[lane + 32 * j]; s += v[j] * v[j]; }
#pragma unroll
    for (int o = 16; o; o >>= 1) s += __shfl_xor_sync(0xffffffffu, s, o);
    float inv = 1.0f / (sqrtf(s) + EPS);
    float* dst = g_proto + mod * 65536 + row * 256;
#pragma unroll
    for (int j = 0; j < 8; j++) dst[lane + 32 * j] = v[j] * inv;
}

// per-row 1/(||x||+eps): warp per row
__global__ void k_xnorm(const float* __restrict__ f_rgb, const float* __restrict__ f_sn) {
    int warp = (blockIdx.x * blockDim.x + threadIdx.x) >> 5;
    int lane = threadIdx.x & 31;
    if (warp >= 32768) return;
    int mod = warp >> 14, lrow = warp & 16383;
    const float* src = (mod ? f_sn : f_rgb) + (size_t)lrow * 256;
    float s = 0.f;
#pragma unroll
    for (int j = 0; j < 8; j++) { float x = src[lane + 32 * j]; s += x * x; }
#pragma unroll
    for (int o = 16; o; o >>= 1) s += __shfl_xor_sync(0xffffffffu, s, o);
    if (lane == 0) g_xinv[warp] = 1.0f / (sqrtf(s) + EPS);
}

// ---------------- GEMM1: sim = Xhat @ Phat^T ; M = exp(20*sim) ----------------
// CTA: 64 rows x 256 cols, D-loop in chunks of 32. 256 thr, 8x8 microtile.
__global__ __launch_bounds__(256, 2)
void k_gemm_sim(const float* __restrict__ f_rgb, const float* __restrict__ f_sn,
                float* __restrict__ out) {
    __shared__ float Xs[32][65];
    __shared__ float Ps[32][257];
    int t = threadIdx.x;
    int ct = t & 31, rt = t >> 5;
    int row0 = blockIdx.x * 64;          // global row in [0,32768)
    int mod = row0 >> 14;
    int lrow0 = row0 & 16383;
    const float* X = (mod ? f_sn : f_rgb) + (size_t)lrow0 * 256;
    const float* P = g_proto + mod * 65536;
    float acc[8][8];
#pragma unroll
    for (int r = 0; r < 8; r++)
#pragma unroll
        for (int q = 0; q < 8; q++) acc[r][q] = 0.f;

    for (int dd = 0; dd < 256; dd += 32) {
#pragma unroll
        for (int i = 0; i < 8; i++) {          // X tile 64x32
            int m = (t >> 5) + 8 * i, j = t & 31;
            Xs[j][m] = X[m * 256 + dd + j];
        }
#pragma unroll
        for (int i = 0; i < 32; i++) {         // P tile 256x32
            int k = (t >> 5) + 8 * i, j = t & 31;
            Ps[j][k] = P[k * 256 + dd + j];
        }
        __syncthreads();
#pragma unroll
        for (int j = 0; j < 32; j++) {
            float a_[8], b_[8];
#pragma unroll
            for (int r = 0; r < 8; r++) a_[r] = Xs[j][rt * 8 + r];
#pragma unroll
            for (int q = 0; q < 8; q++) b_[q] = Ps[j][ct + 32 * q];
#pragma unroll
            for (int r = 0; r < 8; r++)
#pragma unroll
                for (int q = 0; q < 8; q++) acc[r][q] = fmaf(a_[r], b_[q], acc[r][q]);
        }
        __syncthreads();
    }
    float* sim_out = out + (size_t)(4 + mod) * SEG + (size_t)lrow0 * 256;
    float psum = 0.f;
#pragma unroll
    for (int r = 0; r < 8; r++) {
        int m = rt * 8 + r;
        float xi = g_xinv[row0 + m];
#pragma unroll
        for (int q = 0; q < 8; q++) {
            int col = ct + 32 * q;
            float s = acc[r][q] * xi;
            sim_out[m * 256 + col] = s;
            float mm = exp20(s);
            g_M[(size_t)(row0 + m) * 256 + col] = mm;
            psum += mm;
        }
    }
#pragma unroll
    for (int o = 16; o; o >>= 1) psum += __shfl_xor_sync(0xffffffffu, psum, o);
    if ((t & 31) == 0) atomicAdd(&g_bs[row0 >> 10], psum);
}

__global__ void k_init_uv() {
    int i = blockIdx.x * blockDim.x + threadIdx.x;
    if (i < 32768)      g_u[i] = 1.0f / (g_bs[i >> 10] + EPS);
    else if (i < 40960) g_v[i - 32768] = 1.0f;
}

// ---------------- one sinkhorn iteration, single pass over M ----------------
// row step (update u) fused with column partial sums (M^T u') accumulation.
__global__ __launch_bounds__(256)
void k_sink_row() {
    __shared__ float vs[256];
    __shared__ float colacc[256];
    int t = threadIdx.x, lane = t & 31, w = t >> 5;
    int row0 = blockIdx.x * 64;
    int bm = row0 >> 10;                        // (mod,batch) in [0,32)
    vs[t] = g_v[bm * 256 + t];
    colacc[t] = 0.f;
    __syncthreads();
    float4 vr0 = *(const float4*)&vs[4 * lane];
    float4 vr1 = *(const float4*)&vs[128 + 4 * lane];
    float4 c0 = {0, 0, 0, 0}, c1 = {0, 0, 0, 0};
#pragma unroll
    for (int r = 0; r < 8; r++) {
        int n = row0 + w * 8 + r;
        const float4* Mr = (const float4*)(g_M + (size_t)n * 256);
        float4 m0 = Mr[lane], m1 = Mr[32 + lane];
        float dot = m0.x * vr0.x + m0.y * vr0.y + m0.z * vr0.z + m0.w * vr0.w
                  + m1.x * vr1.x + m1.y * vr1.y + m1.z * vr1.z + m1.w * vr1.w;
#pragma unroll
        for (int o = 16; o; o >>= 1) dot += __shfl_xor_sync(0xffffffffu, dot, o);
        float u = g_u[n];
        float un = u * TR / (u * dot + EPS);
        if (lane == 0) g_u[n] = un;
        c0.x += m0.x * un; c0.y += m0.y * un; c0.z += m0.z * un; c0.w += m0.w * un;
        c1.x += m1.x * un; c1.y += m1.y * un; c1.z += m1.z * un; c1.w += m1.w * un;
    }
    atomicAdd(&colacc[4 * lane + 0], c0.x); atomicAdd(&colacc[4 * lane + 1], c0.y);
    atomicAdd(&colacc[4 * lane + 2], c0.z); atomicAdd(&colacc[4 * lane + 3], c0.w);
    atomicAdd(&colacc[128 + 4 * lane + 0], c1.x); atomicAdd(&colacc[128 + 4 * lane + 1], c1.y);
    atomicAdd(&colacc[128 + 4 * lane + 2], c1.z); atomicAdd(&colacc[128 + 4 * lane + 3], c1.w);
    __syncthreads();
    atomicAdd(&g_colacc[bm * 256 + t], colacc[t]);
}

__global__ void k_sink_col() {
    int i = blockIdx.x * blockDim.x + threadIdx.x;
    if (i < 8192) {
        float v = g_v[i], a = g_colacc[i];
        g_v[i] = v * TC / (v * a + EPS);
        g_colacc[i] = 0.f;
    }
}

// ---------------- final row-normalize, write assign, accumulate colsums ----------------
__global__ __launch_bounds__(256)
void k_final(float* __restrict__ out) {
    __shared__ float vs[256];
    __shared__ float colacc[256];
    int t = threadIdx.x, lane = t & 31, w = t >> 5;
    int row0 = blockIdx.x * 64;
    int bm = row0 >> 10;
    int mod = row0 >> 14;
    vs[t] = g_v[bm * 256 + t];
    colacc[t] = 0.f;
    __syncthreads();
    float4 vr0 = *(const float4*)&vs[4 * lane];
    float4 vr1 = *(const float4*)&vs[128 + 4 * lane];
    float4 c0 = {0, 0, 0, 0}, c1 = {0, 0, 0, 0};
    float* aout = out + (size_t)(2 + mod) * SEG;
#pragma unroll
    for (int r = 0; r < 8; r++) {
        int n = row0 + w * 8 + r;
        int lrow = n & 16383;
        const float4* Mr = (const float4*)(g_M + (size_t)n * 256);
        float4 m0 = Mr[lane], m1 = Mr[32 + lane];
        float dot = m0.x * vr0.x + m0.y * vr0.y + m0.z * vr0.z + m0.w * vr0.w
                  + m1.x * vr1.x + m1.y * vr1.y + m1.z * vr1.z + m1.w * vr1.w;
#pragma unroll
        for (int o = 16; o; o >>= 1) dot += __shfl_xor_sync(0xffffffffu, dot, o);
        float u = g_u[n];
        float un = u / (u * dot + EPS);
        float4 a0, a1;
        a0.x = m0.x * un * vr0.x; a0.y = m0.y * un * vr0.y;
        a0.z = m0.z * un * vr0.z; a0.w = m0.w * un * vr0.w;
        a1.x = m1.x * un * vr1.x; a1.y = m1.y * un * vr1.y;
        a1.z = m1.z * un * vr1.z; a1.w = m1.w * un * vr1.w;
        *(float4*)(aout + (size_t)lrow * 256 + 4 * lane) = a0;
        *(float4*)(aout + (size_t)lrow * 256 + 128 + 4 * lane) = a1;
        c0.x += a0.x; c0.y += a0.y; c0.z += a0.z; c0.w += a0.w;
        c1.x += a1.x; c1.y += a1.y; c1.z += a1.z; c1.w += a1.w;
    }
    atomicAdd(&colacc[4 * lane + 0], c0.x); atomicAdd(&colacc[4 * lane + 1], c0.y);
    atomicAdd(&colacc[4 * lane + 2], c0.z); atomicAdd(&colacc[4 * lane + 3], c0.w);
    atomicAdd(&colacc[128 + 4 * lane + 0], c1.x); atomicAdd(&colacc[128 + 4 * lane + 1], c1.y);
    atomicAdd(&colacc[128 + 4 * lane + 2], c1.z); atomicAdd(&colacc[128 + 4 * lane + 3], c1.w);
    __syncthreads();
    atomicAdd(&g_csum2[bm * 256 + t], colacc[t]);
}

// sem_consistency = 1 - clip(sum_b <colsum_rgb[b], colsum_sn[b]> / (B*N*N))
__global__ void k_consist(float* __restrict__ out) {
    __shared__ float red[8];
    int t = threadIdx.x;
    float acc = 0.f;
#pragma unroll
    for (int b = 0; b < 16; b++)
        acc += g_csum2[b * 256 + t] * g_csum2[4096 + b * 256 + t];
#pragma unroll
    for (int o = 16; o; o >>= 1) acc += __shfl_xor_sync(0xffffffffu, acc, o);
    if ((t & 31) == 0) red[t >> 5] = acc;
    __syncthreads();
    if (t == 0) {
        float tot = 0.f;
        for (int i = 0; i < 8; i++) tot += red[i];
        float m = tot * (1.0f / 16777216.0f);
        m = fminf(fmaxf(m, 0.f), 1.f);
        out[(size_t)6 * SEG] = 1.0f - m;
    }
}

// ---------------- GEMM2: z = assign @ Phat ----------------
__global__ __launch_bounds__(256, 2)
void k_gemm_z(float* __restrict__ out) {
    __shared__ float As[32][65];
    __shared__ float Bs[32][256];
    int t = threadIdx.x;
    int ct = t & 31, rt = t >> 5;
    int row0 = blockIdx.x * 64;
    int mod = row0 >> 14;
    int lrow0 = row0 & 16383;
    const float* A = out + (size_t)(2 + mod) * SEG + (size_t)lrow0 * 256;
    const float* P = g_proto + mod * 65536;
    float acc[8][8];
#pragma unroll
    for (int r = 0; r < 8; r++)
#pragma unroll
        for (int q = 0; q < 8; q++) acc[r][q] = 0.f;

    for (int kk = 0; kk < 256; kk += 32) {
#pragma unroll
        for (int i = 0; i < 8; i++) {          // A tile 64x32
            int m = (t >> 5) + 8 * i, j = t & 31;
            As[j][m] = A[m * 256 + kk + j];
        }
#pragma unroll
        for (int i = 0; i < 32; i++)           // B tile 32x256 (natural)
            Bs[i][t] = P[(kk + i) * 256 + t];
        __syncthreads();
#pragma unroll
        for (int j = 0; j < 32; j++) {
            float a_[8], b_[8];
#pragma unroll
            for (int r = 0; r < 8; r++) a_[r] = As[j][rt * 8 + r];
#pragma unroll
            for (int q = 0; q < 8; q++) b_[q] = Bs[j][ct + 32 * q];
#pragma unroll
            for (int r = 0; r < 8; r++)
#pragma unroll
                for (int q = 0; q < 8; q++) acc[r][q] = fmaf(a_[r], b_[q], acc[r][q]);
        }
        __syncthreads();
    }
    float* zout = out + (size_t)mod * SEG + (size_t)lrow0 * 256;
#pragma unroll
    for (int r = 0; r < 8; r++) {
        int m = rt * 8 + r;
#pragma unroll
        for (int q = 0; q < 8; q++)
            zout[m * 256 + ct + 32 * q] = acc[r][q];
    }
}

// ---------------- launch ----------------
extern "C" void kernel_launch(void* const* d_in, const int* in_sizes, int n_in,
                              void* d_out, int out_size) {
    const float* f_rgb = (const float*)d_in[0];
    const float* f_sn  = (const float*)d_in[1];
    const float* p_rgb = (const float*)d_in[2];
    const float* p_sn  = (const float*)d_in[3];
    float* out = (float*)d_out;

    k_zero<<<32, 256>>>();
    k_proto<<<64, 256>>>(p_rgb, p_sn);
    k_xnorm<<<4096, 256>>>(f_rgb, f_sn);
    k_gemm_sim<<<512, 256>>>(f_rgb, f_sn, out);
    k_init_uv<<<160, 256>>>();
    for (int it = 0; it < 5; it++) {
        k_sink_row<<<512, 256>>>();
        k_sink_col<<<32, 256>>>();
    }
    k_final<<<512, 256>>>(out);
    k_consist<<<1, 256>>>(out);
    k_gemm_z<<<512, 256>>>(out);
}

// round 2
// speedup vs baseline: 1.1298x; 1.1298x over previous
#include <cuda_runtime.h>
#include <math.h>

#define EPS 1e-8f
#define TR  (1.0f/1024.0f)
#define TC  (1.0f/256.0f)
#define SEG 4194304            // 16*1024*256
typedef unsigned long long ull;

// ---------------- scratch (device globals; no allocation) ----------------
__device__ float g_M[8388608];      // exp(sim/tau), [32768 rows][256 cols], 32MB
__device__ float g_proto[131072];   // normalized protos [2][256][256]
__device__ float g_xinv[32768];     // 1/(||x||+eps) per row
__device__ float g_u[32768];
__device__ float g_v[8192];         // [2*16][256]
__device__ float g_colacc[8192];
__device__ float g_csum2[8192];     // colsums of final assign
__device__ float g_bs[32];          // per (mod,batch) sum of M

// exp(20*s) via 2^y with degree-7 Taylor of 2^f — no MUFU
__device__ __forceinline__ float exp20(float s) {
    float y  = s * 28.853900817779268f;      // 20 * log2(e)
    float fl = floorf(y);
    float f  = y - fl;
    float p = 1.5252733804059840e-05f;
    p = fmaf(p, f, 1.5403530393381609e-04f);
    p = fmaf(p, f, 1.3333558146428443e-03f);
    p = fmaf(p, f, 9.6181291076284772e-03f);
    p = fmaf(p, f, 5.5504108664821580e-02f);
    p = fmaf(p, f, 2.4022650695910071e-01f);
    p = fmaf(p, f, 6.9314718055994531e-01f);
    p = fmaf(p, f, 1.0f);
    int e = (int)fl + 127;
    return p * __int_as_float(e << 23);
}

__device__ __forceinline__ ull dup2(float b) {
    ull r;
    asm("mov.b64 %0, {%1, %1};" : "=l"(r) : "f"(b));
    return r;
}
__device__ __forceinline__ void fma2(ull& acc, ull a, ull b) {
    asm("fma.rn.f32x2 %0, %1, %2, %0;" : "+l"(acc) : "l"(a), "l"(b));
}
__device__ __forceinline__ void unpack2(ull v, float& lo, float& hi) {
    asm("mov.b64 {%0, %1}, %2;" : "=f"(lo), "=f"(hi) : "l"(v));
}

// ---------------- tiny init ----------------
__global__ void k_zero() {
    int i = blockIdx.x * blockDim.x + threadIdx.x;
    if (i < 8192) { g_colacc[i] = 0.f; g_csum2[i] = 0.f; }
    if (i < 32)   g_bs[i] = 0.f;
}

// normalize prototypes: warp per row
__global__ void k_proto(const float* __restrict__ p_rgb, const float* __restrict__ p_sn) {
    int warp = (blockIdx.x * blockDim.x + threadIdx.x) >> 5;
    int lane = threadIdx.x & 31;
    if (warp >= 512) return;
    int mod = warp >> 8, row = warp & 255;
    const float* src = (mod ? p_sn : p_rgb) + row * 256;
    float v[8], s = 0.f;
#pragma unroll
    for (int j = 0; j < 8; j++) { v[j] = src[lane + 32 * j]; s += v[j] * v[j]; }
#pragma unroll
    for (int o = 16; o; o >>= 1) s += __shfl_xor_sync(0xffffffffu, s, o);
    float inv = 1.0f / (sqrtf(s) + EPS);
    float* dst = g_proto + mod * 65536 + row * 256;
#pragma unroll
    for (int j = 0; j < 8; j++) dst[lane + 32 * j] = v[j] * inv;
}

// per-row 1/(||x||+eps): warp per row
__global__ void k_xnorm(const float* __restrict__ f_rgb, const float* __restrict__ f_sn) {
    int warp = (blockIdx.x * blockDim.x + threadIdx.x) >> 5;
    int lane = threadIdx.x & 31;
    if (warp >= 32768) return;
    int mod = warp >> 14, lrow = warp & 16383;
    const float* src = (mod ? f_sn : f_rgb) + (size_t)lrow * 256;
    float s = 0.f;
#pragma unroll
    for (int j = 0; j < 8; j++) { float x = src[lane + 32 * j]; s += x * x; }
#pragma unroll
    for (int o = 16; o; o >>= 1) s += __shfl_xor_sync(0xffffffffu, s, o);
    if (lane == 0) g_xinv[warp] = 1.0f / (sqrtf(s) + EPS);
}

// ---------------- GEMM1: sim = Xhat @ Phat^T ; M = exp(20*sim) ----------------
// CTA: 64 rows x 256 cols. 8x8 microtile packed as 4 row-pairs via fma.rn.f32x2.
__global__ __launch_bounds__(256, 2)
void k_gemm_sim(const float* __restrict__ f_rgb, const float* __restrict__ f_sn,
                float* __restrict__ out) {
    __shared__ float Xs[32][66];   // even row stride -> 8B-aligned row pairs
    __shared__ float Ps[32][257];
    int t = threadIdx.x;
    int ct = t & 31, rt = t >> 5;
    int row0 = blockIdx.x * 64;
    int mod = row0 >> 14;
    int lrow0 = row0 & 16383;
    const float* X = (mod ? f_sn : f_rgb) + (size_t)lrow0 * 256;
    const float* P = g_proto + mod * 65536;
    ull acc[4][8];
#pragma unroll
    for (int rp = 0; rp < 4; rp++)
#pragma unroll
        for (int q = 0; q < 8; q++) acc[rp][q] = 0ull;

    for (int dd = 0; dd < 256; dd += 32) {
#pragma unroll
        for (int i = 0; i < 8; i++) {          // X tile 64x32 (transposed into smem)
            int m = (t >> 5) + 8 * i, j = t & 31;
            Xs[j][m] = X[m * 256 + dd + j];
        }
#pragma unroll
        for (int i = 0; i < 32; i++) {         // P tile 256x32 (transposed)
            int k = (t >> 5) + 8 * i, j = t & 31;
            Ps[j][k] = P[k * 256 + dd + j];
        }
        __syncthreads();
#pragma unroll
        for (int j = 0; j < 32; j++) {
            ull a2[4], b2[8];
#pragma unroll
            for (int rp = 0; rp < 4; rp++)
                a2[rp] = *(const ull*)&Xs[j][rt * 8 + 2 * rp];
#pragma unroll
            for (int q = 0; q < 8; q++)
                b2[q] = dup2(Ps[j][ct + 32 * q]);
#pragma unroll
            for (int rp = 0; rp < 4; rp++)
#pragma unroll
                for (int q = 0; q < 8; q++)
                    fma2(acc[rp][q], a2[rp], b2[q]);
        }
        __syncthreads();
    }
    float* sim_out = out + (size_t)(4 + mod) * SEG + (size_t)lrow0 * 256;
    float psum = 0.f;
#pragma unroll
    for (int rp = 0; rp < 4; rp++) {
        int m0 = rt * 8 + 2 * rp;
        float xi0 = g_xinv[row0 + m0];
        float xi1 = g_xinv[row0 + m0 + 1];
#pragma unroll
        for (int q = 0; q < 8; q++) {
            int col = ct + 32 * q;
            float s0, s1;
            unpack2(acc[rp][q], s0, s1);
            s0 *= xi0; s1 *= xi1;
            sim_out[m0 * 256 + col] = s0;
            sim_out[(m0 + 1) * 256 + col] = s1;
            float e0 = exp20(s0), e1 = exp20(s1);
            g_M[(size_t)(row0 + m0) * 256 + col] = e0;
            g_M[(size_t)(row0 + m0 + 1) * 256 + col] = e1;
            psum += e0 + e1;
        }
    }
#pragma unroll
    for (int o = 16; o; o >>= 1) psum += __shfl_xor_sync(0xffffffffu, psum, o);
    if ((t & 31) == 0) atomicAdd(&g_bs[row0 >> 10], psum);
}

__global__ void k_init_uv() {
    int i = blockIdx.x * blockDim.x + threadIdx.x;
    if (i < 32768)      g_u[i] = 1.0f / (g_bs[i >> 10] + EPS);
    else if (i < 40960) g_v[i - 32768] = 1.0f;
}

// ---------------- one sinkhorn iteration, single pass over M ----------------
__global__ __launch_bounds__(256)
void k_sink_row() {
    __shared__ float vs[256];
    __shared__ float colacc[256];
    int t = threadIdx.x, lane = t & 31, w = t >> 5;
    int row0 = blockIdx.x * 64;
    int bm = row0 >> 10;
    vs[t] = g_v[bm * 256 + t];
    colacc[t] = 0.f;
    __syncthreads();
    float4 vr0 = *(const float4*)&vs[4 * lane];
    float4 vr1 = *(const float4*)&vs[128 + 4 * lane];
    float4 c0 = {0, 0, 0, 0}, c1 = {0, 0, 0, 0};
#pragma unroll
    for (int r = 0; r < 8; r++) {
        int n = row0 + w * 8 + r;
        const float4* Mr = (const float4*)(g_M + (size_t)n * 256);
        float4 m0 = Mr[lane], m1 = Mr[32 + lane];
        float dot = m0.x * vr0.x + m0.y * vr0.y + m0.z * vr0.z + m0.w * vr0.w
                  + m1.x * vr1.x + m1.y * vr1.y + m1.z * vr1.z + m1.w * vr1.w;
#pragma unroll
        for (int o = 16; o; o >>= 1) dot += __shfl_xor_sync(0xffffffffu, dot, o);
        float u = g_u[n];
        float un = u * TR / (u * dot + EPS);
        if (lane == 0) g_u[n] = un;
        c0.x += m0.x * un; c0.y += m0.y * un; c0.z += m0.z * un; c0.w += m0.w * un;
        c1.x += m1.x * un; c1.y += m1.y * un; c1.z += m1.z * un; c1.w += m1.w * un;
    }
    atomicAdd(&colacc[4 * lane + 0], c0.x); atomicAdd(&colacc[4 * lane + 1], c0.y);
    atomicAdd(&colacc[4 * lane + 2], c0.z); atomicAdd(&colacc[4 * lane + 3], c0.w);
    atomicAdd(&colacc[128 + 4 * lane + 0], c1.x); atomicAdd(&colacc[128 + 4 * lane + 1], c1.y);
    atomicAdd(&colacc[128 + 4 * lane + 2], c1.z); atomicAdd(&colacc[128 + 4 * lane + 3], c1.w);
    __syncthreads();
    atomicAdd(&g_colacc[bm * 256 + t], colacc[t]);
}

__global__ void k_sink_col() {
    int i = blockIdx.x * blockDim.x + threadIdx.x;
    if (i < 8192) {
        float v = g_v[i], a = g_colacc[i];
        g_v[i] = v * TC / (v * a + EPS);
        g_colacc[i] = 0.f;
    }
}

// ---------------- final row-normalize, write assign, accumulate colsums ----------------
__global__ __launch_bounds__(256)
void k_final(float* __restrict__ out) {
    __shared__ float vs[256];
    __shared__ float colacc[256];
    int t = threadIdx.x, lane = t & 31, w = t >> 5;
    int row0 = blockIdx.x * 64;
    int bm = row0 >> 10;
    int mod = row0 >> 14;
    vs[t] = g_v[bm * 256 + t];
    colacc[t] = 0.f;
    __syncthreads();
    float4 vr0 = *(const float4*)&vs[4 * lane];
    float4 vr1 = *(const float4*)&vs[128 + 4 * lane];
    float4 c0 = {0, 0, 0, 0}, c1 = {0, 0, 0, 0};
    float* aout = out + (size_t)(2 + mod) * SEG;
#pragma unroll
    for (int r = 0; r < 8; r++) {
        int n = row0 + w * 8 + r;
        int lrow = n & 16383;
        const float4* Mr = (const float4*)(g_M + (size_t)n * 256);
        float4 m0 = Mr[lane], m1 = Mr[32 + lane];
        float dot = m0.x * vr0.x + m0.y * vr0.y + m0.z * vr0.z + m0.w * vr0.w
                  + m1.x * vr1.x + m1.y * vr1.y + m1.z * vr1.z + m1.w * vr1.w;
#pragma unroll
        for (int o = 16; o; o >>= 1) dot += __shfl_xor_sync(0xffffffffu, dot, o);
        float u = g_u[n];
        float un = u / (u * dot + EPS);
        float4 a0, a1;
        a0.x = m0.x * un * vr0.x; a0.y = m0.y * un * vr0.y;
        a0.z = m0.z * un * vr0.z; a0.w = m0.w * un * vr0.w;
        a1.x = m1.x * un * vr1.x; a1.y = m1.y * un * vr1.y;
        a1.z = m1.z * un * vr1.z; a1.w = m1.w * un * vr1.w;
        *(float4*)(aout + (size_t)lrow * 256 + 4 * lane) = a0;
        *(float4*)(aout + (size_t)lrow * 256 + 128 + 4 * lane) = a1;
        c0.x += a0.x; c0.y += a0.y; c0.z += a0.z; c0.w += a0.w;
        c1.x += a1.x; c1.y += a1.y; c1.z += a1.z; c1.w += a1.w;
    }
    atomicAdd(&colacc[4 * lane + 0], c0.x); atomicAdd(&colacc[4 * lane + 1], c0.y);
    atomicAdd(&colacc[4 * lane + 2], c0.z); atomicAdd(&colacc[4 * lane + 3], c0.w);
    atomicAdd(&colacc[128 + 4 * lane + 0], c1.x); atomicAdd(&colacc[128 + 4 * lane + 1], c1.y);
    atomicAdd(&colacc[128 + 4 * lane + 2], c1.z); atomicAdd(&colacc[128 + 4 * lane + 3], c1.w);
    __syncthreads();
    atomicAdd(&g_csum2[bm * 256 + t], colacc[t]);
}

// sem_consistency = 1 - clip(sum_b <colsum_rgb[b], colsum_sn[b]> / (B*N*N))
__global__ void k_consist(float* __restrict__ out) {
    __shared__ float red[8];
    int t = threadIdx.x;
    float acc = 0.f;
#pragma unroll
    for (int b = 0; b < 16; b++)
        acc += g_csum2[b * 256 + t] * g_csum2[4096 + b * 256 + t];
#pragma unroll
    for (int o = 16; o; o >>= 1) acc += __shfl_xor_sync(0xffffffffu, acc, o);
    if ((t & 31) == 0) red[t >> 5] = acc;
    __syncthreads();
    if (t == 0) {
        float tot = 0.f;
        for (int i = 0; i < 8; i++) tot += red[i];
        float m = tot * (1.0f / 16777216.0f);
        m = fminf(fmaxf(m, 0.f), 1.f);
        out[(size_t)6 * SEG] = 1.0f - m;
    }
}

// ---------------- GEMM2: z = assign @ Phat (packed f32x2) ----------------
__global__ __launch_bounds__(256, 2)
void k_gemm_z(float* __restrict__ out) {
    __shared__ float As[32][66];
    __shared__ float Bs[32][256];
    int t = threadIdx.x;
    int ct = t & 31, rt = t >> 5;
    int row0 = blockIdx.x * 64;
    int mod = row0 >> 14;
    int lrow0 = row0 & 16383;
    const float* A = out + (size_t)(2 + mod) * SEG + (size_t)lrow0 * 256;
    const float* P = g_proto + mod * 65536;
    ull acc[4][8];
#pragma unroll
    for (int rp = 0; rp < 4; rp++)
#pragma unroll
        for (int q = 0; q < 8; q++) acc[rp][q] = 0ull;

    for (int kk = 0; kk < 256; kk += 32) {
#pragma unroll
        for (int i = 0; i < 8; i++) {          // A tile 64x32 (transposed)
            int m = (t >> 5) + 8 * i, j = t & 31;
            As[j][m] = A[m * 256 + kk + j];
        }
#pragma unroll
        for (int i = 0; i < 32; i++)           // B tile 32x256 (natural)
            Bs[i][t] = P[(kk + i) * 256 + t];
        __syncthreads();
#pragma unroll
        for (int j = 0; j < 32; j++) {
            ull a2[4], b2[8];
#pragma unroll
            for (int rp = 0; rp < 4; rp++)
                a2[rp] = *(const ull*)&As[j][rt * 8 + 2 * rp];
#pragma unroll
            for (int q = 0; q < 8; q++)
                b2[q] = dup2(Bs[j][ct + 32 * q]);
#pragma unroll
            for (int rp = 0; rp < 4; rp++)
#pragma unroll
                for (int q = 0; q < 8; q++)
                    fma2(acc[rp][q], a2[rp], b2[q]);
        }
        __syncthreads();
    }
    float* zout = out + (size_t)mod * SEG + (size_t)lrow0 * 256;
#pragma unroll
    for (int rp = 0; rp < 4; rp++) {
        int m0 = rt * 8 + 2 * rp;
#pragma unroll
        for (int q = 0; q < 8; q++) {
            float s0, s1;
            unpack2(acc[rp][q], s0, s1);
            zout[m0 * 256 + ct + 32 * q] = s0;
            zout[(m0 + 1) * 256 + ct + 32 * q] = s1;
        }
    }
}

// ---------------- launch ----------------
extern "C" void kernel_launch(void* const* d_in, const int* in_sizes, int n_in,
                              void* d_out, int out_size) {
    const float* f_rgb = (const float*)d_in[0];
    const float* f_sn  = (const float*)d_in[1];
    const float* p_rgb = (const float*)d_in[2];
    const float* p_sn  = (const float*)d_in[3];
    float* out = (float*)d_out;

    k_zero<<<32, 256>>>();
    k_proto<<<64, 256>>>(p_rgb, p_sn);
    k_xnorm<<<4096, 256>>>(f_rgb, f_sn);
    k_gemm_sim<<<512, 256>>>(f_rgb, f_sn, out);
    k_init_uv<<<160, 256>>>();
    for (int it = 0; it < 5; it++) {
        k_sink_row<<<512, 256>>>();
        k_sink_col<<<32, 256>>>();
    }
    k_final<<<512, 256>>>(out);
    k_consist<<<1, 256>>>(out);
    k_gemm_z<<<512, 256>>>(out);
}

// round 4
// speedup vs baseline: 1.7141x; 1.5171x over previous
#include <cuda_runtime.h>
#include <cuda_bf16.h>
#include <math.h>
#include <stdint.h>

#define EPS 1e-8f
#define TR  (1.0f/1024.0f)
#define TC  (1.0f/256.0f)
#define SEG 4194304            // 16*1024*256

// ---------------- scratch (device globals; no allocation) ----------------
__device__ float g_M[8388608];              // exp(sim/tau), [32768][256]
__device__ __nv_bfloat16 g_pbh[131072];     // proto normalized, bf16 hi [2][256][256]
__device__ __nv_bfloat16 g_pbl[131072];     // proto normalized, bf16 lo
__device__ float g_xinv[32768];
__device__ float g_u[32768];
__device__ float g_v[8192];
__device__ float g_colacc[8192];
__device__ float g_csum2[8192];
__device__ float g_bs[32];

// exp(20*s) via 2^y, FFMA-only
__device__ __forceinline__ float exp20(float s) {
    float y  = s * 28.853900817779268f;
    float fl = floorf(y);
    float f  = y - fl;
    float p = 1.5252733804059840e-05f;
    p = fmaf(p, f, 1.5403530393381609e-04f);
    p = fmaf(p, f, 1.3333558146428443e-03f);
    p = fmaf(p, f, 9.6181291076284772e-03f);
    p = fmaf(p, f, 5.5504108664821580e-02f);
    p = fmaf(p, f, 2.4022650695910071e-01f);
    p = fmaf(p, f, 6.9314718055994531e-01f);
    p = fmaf(p, f, 1.0f);
    int e = (int)fl + 127;
    return p * __int_as_float(e << 23);
}

__device__ __forceinline__ uint32_t smem_u32(const void* p) {
    uint32_t a;
    asm("{ .reg .u64 t; cvta.to.shared.u64 t, %1; cvt.u32.u64 %0, t; }" : "=r"(a) : "l"(p));
    return a;
}
__device__ __forceinline__ void ldmx4(uint32_t* r, uint32_t addr) {
    asm volatile("ldmatrix.sync.aligned.m8n8.x4.shared.b16 {%0,%1,%2,%3}, [%4];"
                 : "=r"(r[0]), "=r"(r[1]), "=r"(r[2]), "=r"(r[3]) : "r"(addr));
}
__device__ __forceinline__ void mma16816(float* d, const uint32_t* a, const uint32_t* b) {
    asm volatile("mma.sync.aligned.m16n8k16.row.col.f32.bf16.bf16.f32 "
                 "{%0,%1,%2,%3}, {%4,%5,%6,%7}, {%8,%9}, {%0,%1,%2,%3};"
                 : "+f"(d[0]), "+f"(d[1]), "+f"(d[2]), "+f"(d[3])
                 : "r"(a[0]), "r"(a[1]), "r"(a[2]), "r"(a[3]), "r"(b[0]), "r"(b[1]));
}
__device__ __forceinline__ uint32_t pack_bf2(__nv_bfloat16 lo, __nv_bfloat16 hi) {
    __nv_bfloat162 t; t.x = lo; t.y = hi;
    uint32_t r; memcpy(&r, &t, 4); return r;
}
// split float -> (hi bf16, lo bf16)
__device__ __forceinline__ void split_bf(float x, __nv_bfloat16& h, __nv_bfloat16& l) {
    h = __float2bfloat16_rn(x);
    l = __float2bfloat16_rn(x - __bfloat162float(h));
}

// ---------------- tiny init ----------------
__global__ void k_zero() {
    int i = blockIdx.x * blockDim.x + threadIdx.x;
    if (i < 8192) { g_colacc[i] = 0.f; g_csum2[i] = 0.f; }
    if (i < 32)   g_bs[i] = 0.f;
}

// normalize prototypes + bf16 split: warp per row
__global__ void k_proto(const float* __restrict__ p_rgb, const float* __restrict__ p_sn) {
    int warp = (blockIdx.x * blockDim.x + threadIdx.x) >> 5;
    int lane = threadIdx.x & 31;
    if (warp >= 512) return;
    int mod = warp >> 8, row = warp & 255;
    const float* src = (mod ? p_sn : p_rgb) + row * 256;
    float v[8], s = 0.f;
#pragma unroll
    for (int j = 0; j < 8; j++) { v[j] = src[lane + 32 * j]; s += v[j] * v[j]; }
#pragma unroll
    for (int o = 16; o; o >>= 1) s += __shfl_xor_sync(0xffffffffu, s, o);
    float inv = 1.0f / (sqrtf(s) + EPS);
    int base = mod * 65536 + row * 256;
#pragma unroll
    for (int j = 0; j < 8; j++) {
        float val = v[j] * inv;
        __nv_bfloat16 h, l;
        split_bf(val, h, l);
        g_pbh[base + lane + 32 * j] = h;
        g_pbl[base + lane + 32 * j] = l;
    }
}

__global__ void k_xnorm(const float* __restrict__ f_rgb, const float* __restrict__ f_sn) {
    int warp = (blockIdx.x * blockDim.x + threadIdx.x) >> 5;
    int lane = threadIdx.x & 31;
    if (warp >= 32768) return;
    int mod = warp >> 14, lrow = warp & 16383;
    const float* src = (mod ? f_sn : f_rgb) + (size_t)lrow * 256;
    float s = 0.f;
#pragma unroll
    for (int j = 0; j < 8; j++) { float x = src[lane + 32 * j]; s += x * x; }
#pragma unroll
    for (int o = 16; o; o >>= 1) s += __shfl_xor_sync(0xffffffffu, s, o);
    if (lane == 0) g_xinv[warp] = 1.0f / (sqrtf(s) + EPS);
}

// ---------------- shared MMA mainloop ----------------
// CTA tile 128x128, warp tile 32x64 (8 warps). K in 8 chunks of 32.
// A: float rows (row stride 256), split on the fly. B: pre-split proto (Bt[n][k]).
// smem rows padded to 40 bf16 (80B): stride*i mod 128 = 16i -> conflict-free ldmatrix.
#define SROW 40

__device__ __forceinline__ void mma_mainloop(const float* __restrict__ A,
                                             const __nv_bfloat16* __restrict__ Bh,
                                             const __nv_bfloat16* __restrict__ Bl,
                                             float acc[2][8][4], int t) {
    __shared__ __nv_bfloat16 sAh[128 * SROW], sAl[128 * SROW];
    __shared__ __nv_bfloat16 sBh[128 * SROW], sBl[128 * SROW];
    int l = t & 31, w = t >> 5;
    int wm = w >> 1, wn = w & 1;

    uint32_t baseAh = smem_u32(sAh), baseAl = smem_u32(sAl);
    uint32_t baseBh = smem_u32(sBh), baseBl = smem_u32(sBl);

    // per-lane ldmatrix row/col offsets (bytes)
    uint32_t a_off = (uint32_t)(wm * 32 + (l & 7) + 8 * ((l >> 3) & 1)) * (SROW * 2)
                   + ((l >> 4) & 1) * 16;
    uint32_t b_off = (uint32_t)(wn * 64 + (l & 7) + 8 * ((l >> 4) & 1)) * (SROW * 2)
                   + ((l >> 3) & 1) * 16;

    for (int c = 0; c < 8; c++) {
        int dd = c * 32;
        // load+split A chunk: 128 rows x 32 cols, 1024 float4
#pragma unroll
        for (int i = 0; i < 4; i++) {
            int idx = t + 256 * i;
            int row = idx >> 3, c4 = idx & 7;
            float4 v = *(const float4*)(A + (size_t)row * 256 + dd + 4 * c4);
            __nv_bfloat16 hx, lx, hy, ly, hz, lz, hw, lw;
            split_bf(v.x, hx, lx); split_bf(v.y, hy, ly);
            split_bf(v.z, hz, lz); split_bf(v.w, hw, lw);
            uint2 ph, pl;
            ph.x = pack_bf2(hx, hy); ph.y = pack_bf2(hz, hw);
            pl.x = pack_bf2(lx, ly); pl.y = pack_bf2(lz, lw);
            int so = row * SROW + 4 * c4;
            *(uint2*)(sAh + so) = ph;
            *(uint2*)(sAl + so) = pl;
        }
        // load B chunk (already bf16): 2 parts x 128 rows x 32 cols, 1024 uint4
#pragma unroll
        for (int i = 0; i < 4; i++) {
            int idx = t + 256 * i;
            int part = idx >> 9, row = (idx >> 2) & 127, c8 = idx & 3;
            const __nv_bfloat16* src = part ? Bl : Bh;
            uint4 v = *(const uint4*)(src + (size_t)row * 256 + dd + 8 * c8);
            __nv_bfloat16* dst = part ? sBl : sBh;
            *(uint4*)(dst + row * SROW + 8 * c8) = v;
        }
        __syncthreads();
#pragma unroll
        for (int ks = 0; ks < 2; ks++) {
            uint32_t kb = ks * 32;
            uint32_t aH[2][4], aL[2][4];
            ldmx4(aH[0], baseAh + a_off + kb);
            ldmx4(aH[1], baseAh + a_off + 16 * (SROW * 2) + kb);
            ldmx4(aL[0], baseAl + a_off + kb);
            ldmx4(aL[1], baseAl + a_off + 16 * (SROW * 2) + kb);
#pragma unroll
            for (int np = 0; np < 4; np++) {
                uint32_t bo = b_off + (uint32_t)np * 16 * (SROW * 2) + kb;
                uint32_t bH[4], bL[4];
                ldmx4(bH, baseBh + bo);
                ldmx4(bL, baseBl + bo);
#pragma unroll
                for (int tm = 0; tm < 2; tm++) {
                    mma16816(acc[tm][2 * np],     aH[tm], bH);
                    mma16816(acc[tm][2 * np],     aH[tm], bL);
                    mma16816(acc[tm][2 * np],     aL[tm], bH);
                    mma16816(acc[tm][2 * np + 1], aH[tm], bH + 2);
                    mma16816(acc[tm][2 * np + 1], aH[tm], bL + 2);
                    mma16816(acc[tm][2 * np + 1], aL[tm], bH + 2);
                }
            }
        }
        __syncthreads();
    }
}

// ---------------- GEMM1: sim = Xhat @ Phat^T ; M = exp(20*sim) ----------------
__global__ __launch_bounds__(256, 2)
void k_gemm_sim(const float* __restrict__ f_rgb, const float* __restrict__ f_sn,
                float* __restrict__ out) {
    int t = threadIdx.x, l = t & 31, w = t >> 5;
    int wm = w >> 1, wn = w & 1;
    int bx = blockIdx.x;
    int row0 = (bx >> 1) * 128;
    int col0 = (bx & 1) * 128;
    int mod = row0 >> 14, lrow0 = row0 & 16383;
    const float* X = (mod ? f_sn : f_rgb) + (size_t)lrow0 * 256;
    const __nv_bfloat16* Bh = g_pbh + mod * 65536 + (size_t)col0 * 256;
    const __nv_bfloat16* Bl = g_pbl + mod * 65536 + (size_t)col0 * 256;

    float acc[2][8][4];
#pragma unroll
    for (int a = 0; a < 2; a++)
#pragma unroll
        for (int b = 0; b < 8; b++)
#pragma unroll
            for (int d = 0; d < 4; d++) acc[a][b][d] = 0.f;

    mma_mainloop(X, Bh, Bl, acc, t);

    float* simb = out + (size_t)(4 + mod) * SEG;
    float psum = 0.f;
#pragma unroll
    for (int tm = 0; tm < 2; tm++) {
        int r0 = row0 + wm * 32 + tm * 16 + (l >> 2);
        int r1 = r0 + 8;
        float xi0 = g_xinv[r0], xi1 = g_xinv[r1];
        size_t lr0 = (size_t)(r0 & 16383) * 256, lr1 = (size_t)(r1 & 16383) * 256;
        size_t gr0 = (size_t)r0 * 256, gr1 = (size_t)r1 * 256;
#pragma unroll
        for (int nt = 0; nt < 8; nt++) {
            int col = col0 + wn * 64 + nt * 8 + 2 * (l & 3);
            float* d = acc[tm][nt];
            float2 s0 = {d[0] * xi0, d[1] * xi0};
            float2 s1 = {d[2] * xi1, d[3] * xi1};
            *(float2*)(simb + lr0 + col) = s0;
            *(float2*)(simb + lr1 + col) = s1;
            float2 e0 = {exp20(s0.x), exp20(s0.y)};
            float2 e1 = {exp20(s1.x), exp20(s1.y)};
            *(float2*)(g_M + gr0 + col) = e0;
            *(float2*)(g_M + gr1 + col) = e1;
            psum += (e0.x + e0.y) + (e1.x + e1.y);
        }
    }
#pragma unroll
    for (int o = 16; o; o >>= 1) psum += __shfl_xor_sync(0xffffffffu, psum, o);
    if (l == 0) atomicAdd(&g_bs[row0 >> 10], psum);
}

// ---------------- GEMM2: z = assign @ Phat ----------------
// z[m][d] = sum_k A[m][k] * P[k][d]  -> B operand rows are headdim d: need P^T.
// P is [k=256][d=256]; output cols d. Bt[d][k] = P[k][d] -> that's proto transposed.
// We instead use the identity: proto stored row k gives P[k][:]. For mma row.col we
// need Bt[n=d][k]. Build it once into split form? Cheaper: reuse k_proto storage
// transposed at write time is wrong for GEMM1. So store a second transposed copy.
__device__ __nv_bfloat16 g_pth[131072];     // proto^T hi: [2][d=256][k=256]
__device__ __nv_bfloat16 g_ptl[131072];

__global__ void k_proto_t() {
    // transpose g_pbh/g_pbl (2 x 256x256) into g_pth/g_ptl
    int i = blockIdx.x * blockDim.x + threadIdx.x;     // 131072 threads
    int mod = i >> 16, rem = i & 65535;
    int kr = rem >> 8, dc = rem & 255;
    g_pth[mod * 65536 + dc * 256 + kr] = g_pbh[i];
    g_ptl[mod * 65536 + dc * 256 + kr] = g_pbl[i];
}

__global__ __launch_bounds__(256, 2)
void k_gemm_z(float* __restrict__ out) {
    int t = threadIdx.x, l = t & 31, w = t >> 5;
    int wm = w >> 1, wn = w & 1;
    int bx = blockIdx.x;
    int row0 = (bx >> 1) * 128;
    int col0 = (bx & 1) * 128;
    int mod = row0 >> 14, lrow0 = row0 & 16383;
    const float* A = out + (size_t)(2 + mod) * SEG + (size_t)lrow0 * 256;
    const __nv_bfloat16* Bh = g_pth + mod * 65536 + (size_t)col0 * 256;
    const __nv_bfloat16* Bl = g_ptl + mod * 65536 + (size_t)col0 * 256;

    float acc[2][8][4];
#pragma unroll
    for (int a = 0; a < 2; a++)
#pragma unroll
        for (int b = 0; b < 8; b++)
#pragma unroll
            for (int d = 0; d < 4; d++) acc[a][b][d] = 0.f;

    mma_mainloop(A, Bh, Bl, acc, t);

    float* zb = out + (size_t)mod * SEG;
#pragma unroll
    for (int tm = 0; tm < 2; tm++) {
        int r0 = row0 + wm * 32 + tm * 16 + (l >> 2);
        size_t lr0 = (size_t)(r0 & 16383) * 256, lr1 = lr0 + 8 * 256;
#pragma unroll
        for (int nt = 0; nt < 8; nt++) {
            int col = col0 + wn * 64 + nt * 8 + 2 * (l & 3);
            float* d = acc[tm][nt];
            float2 v0 = {d[0], d[1]}, v1 = {d[2], d[3]};
            *(float2*)(zb + lr0 + col) = v0;
            *(float2*)(zb + lr1 + col) = v1;
        }
    }
}

__global__ void k_init_uv() {
    int i = blockIdx.x * blockDim.x + threadIdx.x;
    if (i < 32768)      g_u[i] = 1.0f / (g_bs[i >> 10] + EPS);
    else if (i < 40960) g_v[i - 32768] = 1.0f;
}

// ---------------- sinkhorn iteration (single pass over M) ----------------
__global__ __launch_bounds__(256)
void k_sink_row() {
    __shared__ float vs[256];
    __shared__ float colacc[256];
    int t = threadIdx.x, lane = t & 31, w = t >> 5;
    int row0 = blockIdx.x * 64;
    int bm = row0 >> 10;
    vs[t] = g_v[bm * 256 + t];
    colacc[t] = 0.f;
    __syncthreads();
    float4 vr0 = *(const float4*)&vs[4 * lane];
    float4 vr1 = *(const float4*)&vs[128 + 4 * lane];
    float4 c0 = {0, 0, 0, 0}, c1 = {0, 0, 0, 0};
#pragma unroll
    for (int r = 0; r < 8; r++) {
        int n = row0 + w * 8 + r;
        const float4* Mr = (const float4*)(g_M + (size_t)n * 256);
        float4 m0 = Mr[lane], m1 = Mr[32 + lane];
        float dot = m0.x * vr0.x + m0.y * vr0.y + m0.z * vr0.z + m0.w * vr0.w
                  + m1.x * vr1.x + m1.y * vr1.y + m1.z * vr1.z + m1.w * vr1.w;
#pragma unroll
        for (int o = 16; o; o >>= 1) dot += __shfl_xor_sync(0xffffffffu, dot, o);
        float u = g_u[n];
        float un = u * TR / (u * dot + EPS);
        if (lane == 0) g_u[n] = un;
        c0.x += m0.x * un; c0.y += m0.y * un; c0.z += m0.z * un; c0.w += m0.w * un;
        c1.x += m1.x * un; c1.y += m1.y * un; c1.z += m1.z * un; c1.w += m1.w * un;
    }
    atomicAdd(&colacc[4 * lane + 0], c0.x); atomicAdd(&colacc[4 * lane + 1], c0.y);
    atomicAdd(&colacc[4 * lane + 2], c0.z); atomicAdd(&colacc[4 * lane + 3], c0.w);
    atomicAdd(&colacc[128 + 4 * lane + 0], c1.x); atomicAdd(&colacc[128 + 4 * lane + 1], c1.y);
    atomicAdd(&colacc[128 + 4 * lane + 2], c1.z); atomicAdd(&colacc[128 + 4 * lane + 3], c1.w);
    __syncthreads();
    atomicAdd(&g_colacc[bm * 256 + t], colacc[t]);
}

__global__ void k_sink_col() {
    int i = blockIdx.x * blockDim.x + threadIdx.x;
    if (i < 8192) {
        float v = g_v[i], a = g_colacc[i];
        g_v[i] = v * TC / (v * a + EPS);
        g_colacc[i] = 0.f;
    }
}

// ---------------- final row-normalize, write assign, accumulate colsums ----------------
__global__ __launch_bounds__(256)
void k_final(float* __restrict__ out) {
    __shared__ float vs[256];
    __shared__ float colacc[256];
    int t = threadIdx.x, lane = t & 31, w = t >> 5;
    int row0 = blockIdx.x * 64;
    int bm = row0 >> 10;
    int mod = row0 >> 14;
    vs[t] = g_v[bm * 256 + t];
    colacc[t] = 0.f;
    __syncthreads();
    float4 vr0 = *(const float4*)&vs[4 * lane];
    float4 vr1 = *(const float4*)&vs[128 + 4 * lane];
    float4 c0 = {0, 0, 0, 0}, c1 = {0, 0, 0, 0};
    float* aout = out + (size_t)(2 + mod) * SEG;
#pragma unroll
    for (int r = 0; r < 8; r++) {
        int n = row0 + w * 8 + r;
        int lrow = n & 16383;
        const float4* Mr = (const float4*)(g_M + (size_t)n * 256);
        float4 m0 = Mr[lane], m1 = Mr[32 + lane];
        float dot = m0.x * vr0.x + m0.y * vr0.y + m0.z * vr0.z + m0.w * vr0.w
                  + m1.x * vr1.x + m1.y * vr1.y + m1.z * vr1.z + m1.w * vr1.w;
#pragma unroll
        for (int o = 16; o; o >>= 1) dot += __shfl_xor_sync(0xffffffffu, dot, o);
        float u = g_u[n];
        float un = u / (u * dot + EPS);
        float4 a0, a1;
        a0.x = m0.x * un * vr0.x; a0.y = m0.y * un * vr0.y;
        a0.z = m0.z * un * vr0.z; a0.w = m0.w * un * vr0.w;
        a1.x = m1.x * un * vr1.x; a1.y = m1.y * un * vr1.y;
        a1.z = m1.z * un * vr1.z; a1.w = m1.w * un * vr1.w;
        *(float4*)(aout + (size_t)lrow * 256 + 4 * lane) = a0;
        *(float4*)(aout + (size_t)lrow * 256 + 128 + 4 * lane) = a1;
        c0.x += a0.x; c0.y += a0.y; c0.z += a0.z; c0.w += a0.w;
        c1.x += a1.x; c1.y += a1.y; c1.z += a1.z; c1.w += a1.w;
    }
    atomicAdd(&colacc[4 * lane + 0], c0.x); atomicAdd(&colacc[4 * lane + 1], c0.y);
    atomicAdd(&colacc[4 * lane + 2], c0.z); atomicAdd(&colacc[4 * lane + 3], c0.w);
    atomicAdd(&colacc[128 + 4 * lane + 0], c1.x); atomicAdd(&colacc[128 + 4 * lane + 1], c1.y);
    atomicAdd(&colacc[128 + 4 * lane + 2], c1.z); atomicAdd(&colacc[128 + 4 * lane + 3], c1.w);
    __syncthreads();
    atomicAdd(&g_csum2[bm * 256 + t], colacc[t]);
}

__global__ void k_consist(float* __restrict__ out) {
    __shared__ float red[8];
    int t = threadIdx.x;
    float acc = 0.f;
#pragma unroll
    for (int b = 0; b < 16; b++)
        acc += g_csum2[b * 256 + t] * g_csum2[4096 + b * 256 + t];
#pragma unroll
    for (int o = 16; o; o >>= 1) acc += __shfl_xor_sync(0xffffffffu, acc, o);
    if ((t & 31) == 0) red[t >> 5] = acc;
    __syncthreads();
    if (t == 0) {
        float tot = 0.f;
        for (int i = 0; i < 8; i++) tot += red[i];
        float m = tot * (1.0f / 16777216.0f);
        m = fminf(fmaxf(m, 0.f), 1.f);
        out[(size_t)6 * SEG] = 1.0f - m;
    }
}

// ---------------- launch ----------------
extern "C" void kernel_launch(void* const* d_in, const int* in_sizes, int n_in,
                              void* d_out, int out_size) {
    const float* f_rgb = (const float*)d_in[0];
    const float* f_sn  = (const float*)d_in[1];
    const float* p_rgb = (const float*)d_in[2];
    const float* p_sn  = (const float*)d_in[3];
    float* out = (float*)d_out;

    k_zero<<<32, 256>>>();
    k_proto<<<64, 256>>>(p_rgb, p_sn);
    k_proto_t<<<512, 256>>>();
    k_xnorm<<<4096, 256>>>(f_rgb, f_sn);
    k_gemm_sim<<<512, 256>>>(f_rgb, f_sn, out);
    k_init_uv<<<160, 256>>>();
    for (int it = 0; it < 5; it++) {
        k_sink_row<<<512, 256>>>();
        k_sink_col<<<32, 256>>>();
    }
    k_final<<<512, 256>>>(out);
    k_consist<<<1, 256>>>(out);
    k_gemm_z<<<512, 256>>>(out);
}